// round 5
// baseline (speedup 1.0000x reference)
#include <cuda_runtime.h>
#include <cuda_bf16.h>
#include <math.h>
#include <stdint.h>

#define NB 2
#define LQ 2048
#define SK 2048
#define HH 8
#define DD 64
#define NHT (NB*HH)
#define NHLD (NB*HH*LQ*DD)   // 2,097,152
#define NROWS (NHT*LQ)       // 32768

// Scratch (layout [n][h][row][d])
__device__ __align__(256) __nv_bfloat16 g_Qhi[NHLD];
__device__ __align__(256) __nv_bfloat16 g_Qlo[NHLD];
__device__ __align__(256) __nv_bfloat16 g_Khi[NHLD];
__device__ __align__(256) __nv_bfloat16 g_Klo[NHLD];
__device__ __align__(256) float g_kpart[NHT*8*DD];
__device__ __align__(256) float g_ksum[NHT*DD];
__device__ __align__(256) unsigned int g_rowmax[NROWS];

// ---------------------------------------------------------------------------
// PTX helpers
// ---------------------------------------------------------------------------
__device__ __forceinline__ uint32_t smem_u32_of(const void* p) {
    uint32_t a;
    asm("{ .reg .u64 t; cvta.to.shared.u64 t, %1; cvt.u32.u64 %0, t; }" : "=r"(a) : "l"(p));
    return a;
}
#define LDM4(r, addr) \
    asm volatile("ldmatrix.sync.aligned.m8n8.x4.shared.b16 {%0,%1,%2,%3}, [%4];" \
        : "=r"((r)[0]), "=r"((r)[1]), "=r"((r)[2]), "=r"((r)[3]) : "r"(addr))
#define MMA16816(c, a0, a1, a2, a3, b0, b1) \
    asm volatile("mma.sync.aligned.m16n8k16.row.col.f32.bf16.bf16.f32 " \
        "{%0,%1,%2,%3}, {%4,%5,%6,%7}, {%8,%9}, {%0,%1,%2,%3};" \
        : "+f"((c)[0]), "+f"((c)[1]), "+f"((c)[2]), "+f"((c)[3]) \
        : "r"(a0), "r"(a1), "r"(a2), "r"(a3), "r"(b0), "r"(b1))
#define CPA16(s, g) \
    asm volatile("cp.async.cg.shared.global [%0], [%1], 16;" :: "r"(s), "l"(g))
#define CPC()  asm volatile("cp.async.commit_group;" ::: "memory")
#define CPW1() asm volatile("cp.async.wait_group 1;" ::: "memory")
#define CPW0() asm volatile("cp.async.wait_group 0;" ::: "memory")

// SMEM byte offsets (dynamic smem)
#define A_HI_OFF 0
#define A_LO_OFF 16384
#define B_OFF    32768            // + buf*32768 ; hi at +0, lo at +16384
#define SMEM_TOTAL 98304

// ---------------------------------------------------------------------------
// Kernel A: feature map + mask + [n,l,h,d]->[n,h,l,d] + bf16 hi/lo split
// Also zeroes g_rowmax for the main kernel's atomicMax.
// ---------------------------------------------------------------------------
__global__ __launch_bounds__(256) void prep_kernel(
    const float* __restrict__ q, const float* __restrict__ k,
    const float* __restrict__ qm, const float* __restrict__ km)
{
    int idx = blockIdx.x * 256 + threadIdx.x;      // pair index
    if (idx < NROWS) g_rowmax[idx] = 0u;

    int dp = idx & 31;
    int l  = (idx >> 5) & 2047;
    int h  = (idx >> 16) & 7;
    int n  = idx >> 19;
    int srcp = (((n * 2048 + l) * 8 + h) << 5) + dp;

    float2 qv = ((const float2*)q)[srcp];
    float2 kv = ((const float2*)k)[srcp];
    float qmv = qm[n * 2048 + l];
    float kmv = km[n * 2048 + l];

    float phqx = ((qv.x > 0.f) ? (qv.x + 1.f) : __expf(qv.x)) * qmv;
    float phqy = ((qv.y > 0.f) ? (qv.y + 1.f) : __expf(qv.y)) * qmv;
    float phkx = ((kv.x > 0.f) ? (kv.x + 1.f) : __expf(kv.x)) * kmv;
    float phky = ((kv.y > 0.f) ? (kv.y + 1.f) : __expf(kv.y)) * kmv;

    __nv_bfloat16 qhx = __float2bfloat16(phqx), qhy = __float2bfloat16(phqy);
    __nv_bfloat16 khx = __float2bfloat16(phkx), khy = __float2bfloat16(phky);
    __nv_bfloat162 qh2; qh2.x = qhx; qh2.y = qhy;
    __nv_bfloat162 kh2; kh2.x = khx; kh2.y = khy;
    __nv_bfloat162 ql2; ql2.x = __float2bfloat16(phqx - __bfloat162float(qhx));
                        ql2.y = __float2bfloat16(phqy - __bfloat162float(qhy));
    __nv_bfloat162 kl2; kl2.x = __float2bfloat16(phkx - __bfloat162float(khx));
                        kl2.y = __float2bfloat16(phky - __bfloat162float(khy));

    ((__nv_bfloat162*)g_Qhi)[idx] = qh2;
    ((__nv_bfloat162*)g_Qlo)[idx] = ql2;
    ((__nv_bfloat162*)g_Khi)[idx] = kh2;
    ((__nv_bfloat162*)g_Klo)[idx] = kl2;
}

// ---------------------------------------------------------------------------
// Kernel B1/B2: Ksum[n,h,d] = sum_s phiK
// ---------------------------------------------------------------------------
__global__ __launch_bounds__(256) void ksum_part_kernel()
{
    int nh = blockIdx.x >> 3;
    int ch = blockIdx.x & 7;
    int tid = threadIdx.x;
    int dp = tid & 31;
    int g  = tid >> 5;
    const uint32_t* bh = (const uint32_t*)(g_Khi + (size_t)nh * SK * DD) + (ch * 256) * 32;
    const uint32_t* bl = (const uint32_t*)(g_Klo + (size_t)nh * SK * DD) + (ch * 256) * 32;
    float s0 = 0.f, s1 = 0.f;
    for (int ss = g; ss < 256; ss += 8) {
        uint32_t vh = bh[ss * 32 + dp];
        uint32_t vl = bl[ss * 32 + dp];
        float2 fh = __bfloat1622float2(*(__nv_bfloat162*)&vh);
        float2 fl = __bfloat1622float2(*(__nv_bfloat162*)&vl);
        s0 += fh.x + fl.x;
        s1 += fh.y + fl.y;
    }
    __shared__ float r0[256], r1[256];
    r0[tid] = s0; r1[tid] = s1;
    __syncthreads();
    if (tid < 32) {
        float a0 = 0.f, a1 = 0.f;
        #pragma unroll
        for (int j = 0; j < 8; j++) { a0 += r0[tid + j * 32]; a1 += r1[tid + j * 32]; }
        g_kpart[(nh * 8 + ch) * 64 + tid * 2]     = a0;
        g_kpart[(nh * 8 + ch) * 64 + tid * 2 + 1] = a1;
    }
}

__global__ __launch_bounds__(64) void ksum_final_kernel()
{
    int nh = blockIdx.x;
    int d = threadIdx.x;
    float s = 0.f;
    #pragma unroll
    for (int c = 0; c < 8; c++) s += g_kpart[(nh * 8 + c) * 64 + d];
    g_ksum[nh * 64 + d] = s;
}

// ---------------------------------------------------------------------------
// Kernel C: HMMA score GEMM, pass-major ordering, s-split across gridDim.z.
// grid=(16 ltile, 16 nh, 2 shalf), block=256 (8 warps 4x2), 2 CTAs/SM.
// Row max accumulated to g_rowmax via atomicMax on uint (scores >= 0).
// ---------------------------------------------------------------------------
__global__ void __launch_bounds__(256, 2) attn_mma_kernel()
{
    extern __shared__ char sm[];
    const uint32_t smu = smem_u32_of(sm);

    const int tid  = threadIdx.x;
    const int lane = tid & 31;
    const int wid  = tid >> 5;
    const int wx   = wid & 1;       // n-block (64 cols)
    const int wy   = wid >> 1;      // m-block (32 rows)
    const int nh   = blockIdx.y;
    const int l0   = blockIdx.x * 128;
    const int ts0  = blockIdx.z * 8;     // first s-tile (of 128 cols)

    // --- A tiles (Q hi/lo): LDG + swizzled STS ---
    {
        const char* qh = (const char*)(g_Qhi + ((size_t)nh * LQ + l0) * DD);
        const char* ql = (const char*)(g_Qlo + ((size_t)nh * LQ + l0) * DD);
        #pragma unroll
        for (int c = tid; c < 1024; c += 256) {
            int row = c >> 3, dc = c & 7;
            uint32_t dst = row * 128 + ((dc ^ (row & 7)) << 4);
            *(uint4*)(sm + A_HI_OFF + dst) = *(const uint4*)(qh + c * 16);
            *(uint4*)(sm + A_LO_OFF + dst) = *(const uint4*)(ql + c * 16);
        }
    }

    const int mat    = lane >> 3;
    const int rin    = lane & 7;
    const int a_row  = wy * 32 + (mat & 1) * 8 + rin;
    const int a_kc   = mat >> 1;
    const int b_roff = wx * 64 + (mat >> 1) * 8 + rin;
    const int b_kc   = mat & 1;

    const char* khi_base = (const char*)(g_Khi + (size_t)nh * SK * DD);
    const char* klo_base = (const char*)(g_Klo + (size_t)nh * SK * DD);

    auto issue_b = [&](int buf, int t) {
        uint32_t bu = smu + B_OFF + buf * 32768;
        const char* gh = khi_base + (size_t)(ts0 + t) * 128 * DD * 2;
        const char* gl = klo_base + (size_t)(ts0 + t) * 128 * DD * 2;
        #pragma unroll
        for (int kk = 0; kk < 4; kk++) {
            int c = tid + kk * 256;
            int row = c >> 3, dc = c & 7;
            uint32_t sw = row * 128 + ((dc ^ (row & 7)) << 4);
            CPA16(bu + sw, gh + c * 16);
            CPA16(bu + 16384 + sw, gl + c * 16);
        }
    };

    issue_b(0, 0); CPC();

    float mA[2] = {0.f, 0.f};
    float mB[2] = {0.f, 0.f};

    for (int t = 0; t < 8; t++) {
        if (t < 7) { issue_b((t + 1) & 1, t + 1); CPC(); CPW1(); }
        else       { CPW0(); }
        __syncthreads();

        const uint32_t Bu = smu + B_OFF + (t & 1) * 32768;
        float acc[2][8][4];
        #pragma unroll
        for (int i = 0; i < 2; i++)
            #pragma unroll
            for (int j = 0; j < 8; j++)
                acc[i][j][0] = acc[i][j][1] = acc[i][j][2] = acc[i][j][3] = 0.f;

        #pragma unroll
        for (int ks = 0; ks < 4; ks++) {
            const int kb = ks * 2;
            uint32_t ah[2][4], al[2][4];
            #pragma unroll
            for (int i = 0; i < 2; i++) {
                int ar = a_row + 16 * i;
                uint32_t ad = smu + ar * 128 + (((a_kc + kb) ^ (ar & 7)) << 4);
                LDM4(ah[i], ad + A_HI_OFF);
                LDM4(al[i], ad + A_LO_OFF);
            }
            #pragma unroll
            for (int jph = 0; jph < 2; jph++) {
                uint32_t rh[2][4], rl[2][4];
                #pragma unroll
                for (int p = 0; p < 2; p++) {
                    int br = b_roff + (jph * 2 + p) * 16;
                    uint32_t bd = Bu + br * 128 + (((b_kc + kb) ^ (br & 7)) << 4);
                    LDM4(rh[p], bd);
                    LDM4(rl[p], bd + 16384);
                }
                // pass-major: 8 hh, then 8 hl, then 8 lh (acc chain distance 8)
                #pragma unroll
                for (int p = 0; p < 2; p++)
                    #pragma unroll
                    for (int i = 0; i < 2; i++) {
                        int j = (jph * 2 + p) * 2;
                        MMA16816(acc[i][j],   ah[i][0], ah[i][1], ah[i][2], ah[i][3], rh[p][0], rh[p][1]);
                        MMA16816(acc[i][j+1], ah[i][0], ah[i][1], ah[i][2], ah[i][3], rh[p][2], rh[p][3]);
                    }
                #pragma unroll
                for (int p = 0; p < 2; p++)
                    #pragma unroll
                    for (int i = 0; i < 2; i++) {
                        int j = (jph * 2 + p) * 2;
                        MMA16816(acc[i][j],   ah[i][0], ah[i][1], ah[i][2], ah[i][3], rl[p][0], rl[p][1]);
                        MMA16816(acc[i][j+1], ah[i][0], ah[i][1], ah[i][2], ah[i][3], rl[p][2], rl[p][3]);
                    }
                #pragma unroll
                for (int p = 0; p < 2; p++)
                    #pragma unroll
                    for (int i = 0; i < 2; i++) {
                        int j = (jph * 2 + p) * 2;
                        MMA16816(acc[i][j],   al[i][0], al[i][1], al[i][2], al[i][3], rh[p][0], rh[p][1]);
                        MMA16816(acc[i][j+1], al[i][0], al[i][1], al[i][2], al[i][3], rh[p][2], rh[p][3]);
                    }
            }
        }

        #pragma unroll
        for (int i = 0; i < 2; i++)
            #pragma unroll
            for (int j = 0; j < 8; j++) {
                mA[i] = fmaxf(mA[i], fmaxf(acc[i][j][0], acc[i][j][1]));
                mB[i] = fmaxf(mB[i], fmaxf(acc[i][j][2], acc[i][j][3]));
            }
        __syncthreads();
    }

    // --- reduce max across lane%4, atomicMax to gmem (uint order = float order for >=0) ---
    #pragma unroll
    for (int off = 1; off <= 2; off <<= 1) {
        #pragma unroll
        for (int i = 0; i < 2; i++) {
            mA[i] = fmaxf(mA[i], __shfl_xor_sync(0xffffffff, mA[i], off));
            mB[i] = fmaxf(mB[i], __shfl_xor_sync(0xffffffff, mB[i], off));
        }
    }
    if ((lane & 3) == 0) {
        int r = lane >> 2;
        unsigned int* rm = g_rowmax + nh * LQ + l0;
        #pragma unroll
        for (int i = 0; i < 2; i++) {
            atomicMax(rm + wy * 32 + i * 16 + r,     __float_as_uint(mA[i]));
            atomicMax(rm + wy * 32 + i * 16 + r + 8, __float_as_uint(mB[i]));
        }
    }
}

// ---------------------------------------------------------------------------
// Kernel D: finalize — mean (Ksum trick) + gate + masked-query output.
// One thread per (nh, l). grid = NROWS/256.
// ---------------------------------------------------------------------------
__global__ __launch_bounds__(256) void finalize_kernel(
    const float* __restrict__ queries,
    const float* __restrict__ qmask,
    const float* __restrict__ W,
    const float* __restrict__ bias,
    float* __restrict__ out)
{
    const int tid = threadIdx.x;
    const int g = blockIdx.x * 256 + tid;
    const int nh = g >> 11;
    const int l  = g & 2047;
    const int n  = nh >> 3;
    const int h  = nh & 7;

    __shared__ float ks_s[64];
    if (tid < 64) ks_s[tid] = g_ksum[nh * 64 + tid];
    __syncthreads();

    float mean = 0.f;
    {
        const uint4* ph = (const uint4*)(g_Qhi + (size_t)g * DD);
        const uint4* pl = (const uint4*)(g_Qlo + (size_t)g * DD);
        #pragma unroll
        for (int c = 0; c < 8; c++) {
            uint4 vh = ph[c];
            uint4 vl = pl[c];
            const uint32_t* wh = (const uint32_t*)&vh;
            const uint32_t* wl = (const uint32_t*)&vl;
            #pragma unroll
            for (int w = 0; w < 4; w++) {
                float2 fh = __bfloat1622float2(*(__nv_bfloat162*)&wh[w]);
                float2 fl = __bfloat1622float2(*(__nv_bfloat162*)&wl[w]);
                mean += (fh.x + fl.x) * ks_s[c * 8 + w * 2];
                mean += (fh.y + fl.y) * ks_s[c * 8 + w * 2 + 1];
            }
        }
    }
    mean *= (1.0f / (float)SK);
    float mx = __uint_as_float(g_rowmax[g]);
    float lg = fmaf(mean, W[0], fmaf(mx, W[1], bias[0]));
    float gate = 1.0f / (1.0f + __expf(-lg));
    float s = gate * qmask[n * LQ + l];

    size_t obase = ((((size_t)n * LQ + l) * HH + h) << 6);
    const float4* qs = (const float4*)(queries + obase);
    float4* dst = (float4*)(out + obase);
    #pragma unroll
    for (int j = 0; j < 16; j++) {
        float4 v = qs[j];
        v.x *= s; v.y *= s; v.z *= s; v.w *= s;
        dst[j] = v;
    }
}

// ---------------------------------------------------------------------------
extern "C" void kernel_launch(void* const* d_in, const int* in_sizes, int n_in,
                              void* d_out, int out_size)
{
    const float* queries = (const float*)d_in[0];
    const float* keys    = (const float*)d_in[1];
    const float* q_mask  = (const float*)d_in[3];
    const float* kv_mask = (const float*)d_in[4];
    const float* W       = (const float*)d_in[5];
    const float* b       = (const float*)d_in[6];
    float* out = (float*)d_out;

    prep_kernel<<<(NHLD / 2) / 256, 256>>>(queries, keys, q_mask, kv_mask);
    ksum_part_kernel<<<NHT * 8, 256>>>();
    ksum_final_kernel<<<NHT, 64>>>();

    cudaFuncSetAttribute(attn_mma_kernel,
                         cudaFuncAttributeMaxDynamicSharedMemorySize, SMEM_TOTAL);
    dim3 grid(LQ / 128, NHT, 2);
    attn_mma_kernel<<<grid, 256, SMEM_TOTAL>>>();

    finalize_kernel<<<NROWS / 256, 256>>>(queries, q_mask, W, b, out);
}

// round 6
// speedup vs baseline: 1.9869x; 1.9869x over previous
#include <cuda_runtime.h>
#include <cuda_fp16.h>
#include <math.h>
#include <stdint.h>

#define NB 2
#define LQ 2048
#define SK 2048
#define HH 8
#define DD 64
#define NHT (NB*HH)
#define NHLD (NB*HH*LQ*DD)   // 2,097,152
#define NROWS (NHT*LQ)       // 32768

// Scratch (layout [n][h][row][d]), fp16
__device__ __align__(256) __half g_Qh[NHLD];
__device__ __align__(256) __half g_Kh[NHLD];
__device__ __align__(256) float g_kpart[NHT*8*DD];
__device__ __align__(256) float g_ksum[NHT*DD];
__device__ __align__(256) unsigned int g_rowmax[NROWS];

// ---------------------------------------------------------------------------
// PTX helpers
// ---------------------------------------------------------------------------
__device__ __forceinline__ uint32_t smem_u32_of(const void* p) {
    uint32_t a;
    asm("{ .reg .u64 t; cvta.to.shared.u64 t, %1; cvt.u32.u64 %0, t; }" : "=r"(a) : "l"(p));
    return a;
}
#define LDM4(r, addr) \
    asm volatile("ldmatrix.sync.aligned.m8n8.x4.shared.b16 {%0,%1,%2,%3}, [%4];" \
        : "=r"((r)[0]), "=r"((r)[1]), "=r"((r)[2]), "=r"((r)[3]) : "r"(addr))
#define MMAF16(c, a0, a1, a2, a3, b0, b1) \
    asm volatile("mma.sync.aligned.m16n8k16.row.col.f32.f16.f16.f32 " \
        "{%0,%1,%2,%3}, {%4,%5,%6,%7}, {%8,%9}, {%0,%1,%2,%3};" \
        : "+f"((c)[0]), "+f"((c)[1]), "+f"((c)[2]), "+f"((c)[3]) \
        : "r"(a0), "r"(a1), "r"(a2), "r"(a3), "r"(b0), "r"(b1))
#define CPA16(s, g) \
    asm volatile("cp.async.cg.shared.global [%0], [%1], 16;" :: "r"(s), "l"(g))
#define CPC()  asm volatile("cp.async.commit_group;" ::: "memory")
#define CPW2() asm volatile("cp.async.wait_group 2;" ::: "memory")
#define CPW1() asm volatile("cp.async.wait_group 1;" ::: "memory")
#define CPW0() asm volatile("cp.async.wait_group 0;" ::: "memory")

// SMEM byte offsets
#define A_OFF 0
#define B_OFF 16384             // + buf*16384, 3 stages
#define SMEM_TOTAL 65536

// ---------------------------------------------------------------------------
// Kernel A: feature map + mask + [n,l,h,d]->[n,h,l,d], fp16 out.
// Also zeroes g_rowmax.
// ---------------------------------------------------------------------------
__global__ __launch_bounds__(256) void prep_kernel(
    const float* __restrict__ q, const float* __restrict__ k,
    const float* __restrict__ qm, const float* __restrict__ km)
{
    int idx = blockIdx.x * 256 + threadIdx.x;      // pair index
    if (idx < NROWS) g_rowmax[idx] = 0u;

    int dp = idx & 31;
    int l  = (idx >> 5) & 2047;
    int h  = (idx >> 16) & 7;
    int n  = idx >> 19;
    int srcp = (((n * 2048 + l) * 8 + h) << 5) + dp;

    float2 qv = ((const float2*)q)[srcp];
    float2 kv = ((const float2*)k)[srcp];
    float qmv = qm[n * 2048 + l];
    float kmv = km[n * 2048 + l];

    float phqx = ((qv.x > 0.f) ? (qv.x + 1.f) : __expf(qv.x)) * qmv;
    float phqy = ((qv.y > 0.f) ? (qv.y + 1.f) : __expf(qv.y)) * qmv;
    float phkx = ((kv.x > 0.f) ? (kv.x + 1.f) : __expf(kv.x)) * kmv;
    float phky = ((kv.y > 0.f) ? (kv.y + 1.f) : __expf(kv.y)) * kmv;

    ((__half2*)g_Qh)[idx] = __floats2half2_rn(phqx, phqy);
    ((__half2*)g_Kh)[idx] = __floats2half2_rn(phkx, phky);
}

// ---------------------------------------------------------------------------
// Kernel B1/B2: Ksum[n,h,d] = sum_s phiK (fp32 accumulation)
// ---------------------------------------------------------------------------
__global__ __launch_bounds__(256) void ksum_part_kernel()
{
    int nh = blockIdx.x >> 3;
    int ch = blockIdx.x & 7;
    int tid = threadIdx.x;
    int dp = tid & 31;
    int g  = tid >> 5;
    const __half2* bh = (const __half2*)(g_Kh + (size_t)nh * SK * DD) + (ch * 256) * 32;
    float s0 = 0.f, s1 = 0.f;
    for (int ss = g; ss < 256; ss += 8) {
        float2 f = __half22float2(bh[ss * 32 + dp]);
        s0 += f.x;
        s1 += f.y;
    }
    __shared__ float r0[256], r1[256];
    r0[tid] = s0; r1[tid] = s1;
    __syncthreads();
    if (tid < 32) {
        float a0 = 0.f, a1 = 0.f;
        #pragma unroll
        for (int j = 0; j < 8; j++) { a0 += r0[tid + j * 32]; a1 += r1[tid + j * 32]; }
        g_kpart[(nh * 8 + ch) * 64 + tid * 2]     = a0;
        g_kpart[(nh * 8 + ch) * 64 + tid * 2 + 1] = a1;
    }
}

__global__ __launch_bounds__(64) void ksum_final_kernel()
{
    int nh = blockIdx.x;
    int d = threadIdx.x;
    float s = 0.f;
    #pragma unroll
    for (int c = 0; c < 8; c++) s += g_kpart[(nh * 8 + c) * 64 + d];
    g_ksum[nh * 64 + d] = s;
}

// ---------------------------------------------------------------------------
// Kernel C: fp16 single-pass HMMA score GEMM + row-max via atomicMax.
// grid=(16 ltile, 16 nh, 4 squarter), block=256 (8 warps 4x2), 2 CTAs/SM.
// 3-stage cp.async ring for B tiles (128 s x 64 d fp16, 16KB each).
// ---------------------------------------------------------------------------
#define TILES_PER_CTA 4

__global__ void __launch_bounds__(256, 2) attn_mma_kernel()
{
    extern __shared__ char sm[];
    const uint32_t smu = smem_u32_of(sm);

    const int tid  = threadIdx.x;
    const int lane = tid & 31;
    const int wid  = tid >> 5;
    const int wx   = wid & 1;       // n-block (64 cols)
    const int wy   = wid >> 1;      // m-block (32 rows)
    const int nh   = blockIdx.y;
    const int l0   = blockIdx.x * 128;
    const int ts0  = blockIdx.z * TILES_PER_CTA;

    // --- A tile (Q fp16, 128 x 64): LDG + swizzled STS ---
    {
        const char* qh = (const char*)(g_Qh + ((size_t)nh * LQ + l0) * DD);
        #pragma unroll
        for (int c = tid; c < 1024; c += 256) {
            int row = c >> 3, dc = c & 7;
            uint32_t dst = row * 128 + ((dc ^ (row & 7)) << 4);
            *(uint4*)(sm + A_OFF + dst) = *(const uint4*)(qh + c * 16);
        }
    }

    const int mat    = lane >> 3;
    const int rin    = lane & 7;
    const int a_row  = wy * 32 + (mat & 1) * 8 + rin;
    const int a_kc   = mat >> 1;
    const int b_roff = wx * 64 + (mat >> 1) * 8 + rin;
    const int b_kc   = mat & 1;

    const char* kh_base = (const char*)(g_Kh + (size_t)nh * SK * DD);

    auto issue_b = [&](int t) {
        uint32_t bu = smu + B_OFF + (t % 3) * 16384;
        const char* gk = kh_base + (size_t)(ts0 + t) * 128 * DD * 2;
        #pragma unroll
        for (int kk = 0; kk < 4; kk++) {
            int c = tid + kk * 256;
            int row = c >> 3, dc = c & 7;
            uint32_t sw = row * 128 + ((dc ^ (row & 7)) << 4);
            CPA16(bu + sw, gk + c * 16);
        }
    };

    issue_b(0); CPC();
    issue_b(1); CPC();

    float mA[2] = {0.f, 0.f};
    float mB[2] = {0.f, 0.f};

    for (int t = 0; t < TILES_PER_CTA; t++) {
        if (t + 2 < TILES_PER_CTA)      { issue_b(t + 2); CPC(); CPW2(); }
        else if (t + 1 < TILES_PER_CTA) { CPW1(); }
        else                            { CPW0(); }
        __syncthreads();    // stage t visible; also guards buffer reuse

        const uint32_t Bu = smu + B_OFF + (t % 3) * 16384;
        float acc[2][8][4];
        #pragma unroll
        for (int i = 0; i < 2; i++)
            #pragma unroll
            for (int j = 0; j < 8; j++)
                acc[i][j][0] = acc[i][j][1] = acc[i][j][2] = acc[i][j][3] = 0.f;

        #pragma unroll
        for (int ks = 0; ks < 4; ks++) {
            const int kb = ks * 2;
            uint32_t ah[2][4];
            #pragma unroll
            for (int i = 0; i < 2; i++) {
                int ar = a_row + 16 * i;
                uint32_t ad = smu + A_OFF + ar * 128 + (((a_kc + kb) ^ (ar & 7)) << 4);
                LDM4(ah[i], ad);
            }
            uint32_t rb[4][4];
            #pragma unroll
            for (int jp = 0; jp < 4; jp++) {
                int br = b_roff + jp * 16;
                uint32_t bd = Bu + br * 128 + (((b_kc + kb) ^ (br & 7)) << 4);
                LDM4(rb[jp], bd);
            }
            #pragma unroll
            for (int jp = 0; jp < 4; jp++)
                #pragma unroll
                for (int i = 0; i < 2; i++) {
                    MMAF16(acc[i][jp*2],   ah[i][0], ah[i][1], ah[i][2], ah[i][3], rb[jp][0], rb[jp][1]);
                    MMAF16(acc[i][jp*2+1], ah[i][0], ah[i][1], ah[i][2], ah[i][3], rb[jp][2], rb[jp][3]);
                }
        }

        #pragma unroll
        for (int i = 0; i < 2; i++)
            #pragma unroll
            for (int j = 0; j < 8; j++) {
                mA[i] = fmaxf(mA[i], fmaxf(acc[i][j][0], acc[i][j][1]));
                mB[i] = fmaxf(mB[i], fmaxf(acc[i][j][2], acc[i][j][3]));
            }
        __syncthreads();
    }

    // --- reduce max across lane%4, atomicMax (uint order == float order for >=0) ---
    #pragma unroll
    for (int off = 1; off <= 2; off <<= 1) {
        #pragma unroll
        for (int i = 0; i < 2; i++) {
            mA[i] = fmaxf(mA[i], __shfl_xor_sync(0xffffffff, mA[i], off));
            mB[i] = fmaxf(mB[i], __shfl_xor_sync(0xffffffff, mB[i], off));
        }
    }
    if ((lane & 3) == 0) {
        int r = lane >> 2;
        unsigned int* rm = g_rowmax + nh * LQ + l0;
        #pragma unroll
        for (int i = 0; i < 2; i++) {
            atomicMax(rm + wy * 32 + i * 16 + r,     __float_as_uint(mA[i]));
            atomicMax(rm + wy * 32 + i * 16 + r + 8, __float_as_uint(mB[i]));
        }
    }
}

// ---------------------------------------------------------------------------
// Kernel D: finalize — mean (Ksum trick) + gate + masked-query output.
// ---------------------------------------------------------------------------
__global__ __launch_bounds__(256) void finalize_kernel(
    const float* __restrict__ queries,
    const float* __restrict__ qmask,
    const float* __restrict__ W,
    const float* __restrict__ bias,
    float* __restrict__ out)
{
    const int tid = threadIdx.x;
    const int g = blockIdx.x * 256 + tid;
    const int nh = g >> 11;
    const int l  = g & 2047;
    const int n  = nh >> 3;
    const int h  = nh & 7;

    __shared__ float ks_s[64];
    if (tid < 64) ks_s[tid] = g_ksum[nh * 64 + tid];
    __syncthreads();

    float mean = 0.f;
    {
        const uint4* ph = (const uint4*)(g_Qh + (size_t)g * DD);
        #pragma unroll
        for (int c = 0; c < 4; c++) {
            uint4 v = ph[c];
            const uint32_t* w32 = (const uint32_t*)&v;
            #pragma unroll
            for (int w = 0; w < 4; w++) {
                float2 f = __half22float2(*(const __half2*)&w32[w]);
                mean += f.x * ks_s[c * 16 + w * 2];
                mean += f.y * ks_s[c * 16 + w * 2 + 1];
            }
        }
    }
    mean *= (1.0f / (float)SK);
    float mx = __uint_as_float(g_rowmax[g]);
    float lg = fmaf(mean, W[0], fmaf(mx, W[1], bias[0]));
    float gate = 1.0f / (1.0f + __expf(-lg));
    float s = gate * qmask[n * LQ + l];

    size_t obase = ((((size_t)n * LQ + l) * HH + h) << 6);
    const float4* qs = (const float4*)(queries + obase);
    float4* dst = (float4*)(out + obase);
    #pragma unroll
    for (int j = 0; j < 16; j++) {
        float4 v = qs[j];
        v.x *= s; v.y *= s; v.z *= s; v.w *= s;
        dst[j] = v;
    }
}

// ---------------------------------------------------------------------------
extern "C" void kernel_launch(void* const* d_in, const int* in_sizes, int n_in,
                              void* d_out, int out_size)
{
    const float* queries = (const float*)d_in[0];
    const float* keys    = (const float*)d_in[1];
    const float* q_mask  = (const float*)d_in[3];
    const float* kv_mask = (const float*)d_in[4];
    const float* W       = (const float*)d_in[5];
    const float* b       = (const float*)d_in[6];
    float* out = (float*)d_out;

    prep_kernel<<<(NHLD / 2) / 256, 256>>>(queries, keys, q_mask, kv_mask);
    ksum_part_kernel<<<NHT * 8, 256>>>();
    ksum_final_kernel<<<NHT, 64>>>();

    cudaFuncSetAttribute(attn_mma_kernel,
                         cudaFuncAttributeMaxDynamicSharedMemorySize, SMEM_TOTAL);
    dim3 grid(LQ / 128, NHT, SK / 128 / TILES_PER_CTA);
    attn_mma_kernel<<<grid, 256, SMEM_TOTAL>>>();

    finalize_kernel<<<NROWS / 256, 256>>>(queries, q_mask, W, b, out);
}